// round 7
// baseline (speedup 1.0000x reference)
#include <cuda_runtime.h>
#include <math.h>

#define S     48
#define MD    10
#define H     48
#define NF    60
#define MAXB  65536

// featA config
#define FW    4            // warps per block
#define CH    8            // rows per chunk
#define CHF   (CH*MD)      // 80 floats per traj per chunk
#define CST   82           // padded stride: even (LDS.64 align), 41 float2-banks odd -> conflict-free
#define NCHUNK (S/CH)      // 6

// gemvB config
#define GW    8            // warps per block
#define GT    4            // trajectories per warp

__device__ float g_featT[(size_t)NF * MAXB];   // transposed features [feat][b]
__device__ float g_WtP[H * 68];                // padded transposed W [h][k:68], k>=60 zero

__device__ __forceinline__ float wsum(float v){
  #pragma unroll
  for(int o=16;o;o>>=1) v += __shfl_xor_sync(0xffffffffu,v,o);
  return v;
}
__device__ __forceinline__ float fsqrt_fast(float x){ return x * rsqrtf(x); }

// ============ wprep: transpose W (60x48) -> padded (48x68) once ============
__global__ void wprep(const float* __restrict__ W){
  int idx = blockIdx.x*blockDim.x + threadIdx.x;
  if (idx < H*68){
    int h = idx/68, k = idx - 68*h;
    g_WtP[idx] = (k < NF) ? W[k*H + h] : 0.f;
  }
}

// ============ featA: features, one trajectory per LANE ============
__global__ __launch_bounds__(FW*32, 5)
void featA(const float* __restrict__ coords, const int* __restrict__ lengths, int B)
{
  __shared__ float shC[FW][32*CST];   // 4 x 10.5KB = 42KB

  int w = threadIdx.x >> 5, t = threadIdx.x & 31;
  int base = (blockIdx.x*FW + w)*32;
  if (base >= B) return;
  int tmax = B - base; if (tmax > 32) tmax = 32;
  int b = base + t;
  bool act = (t < tmax);
  int n = act ? lengths[b] : 4;
  int m = n - 1, half = m >> 1;

  float* myrow = shC[w] + t*CST;
  float cur[MD], pd[MD], su[MD];
  float pinv = 0.f;
  float sc=0.f, scq=0.f, s_dm=0.f, s_dmsq=0.f, s_f=0.f, s_s=0.f, s_usq=0.f;
  float s_curv=0.f, s_curvsq=0.f, s_cos=0.f, s_neg=0.f;
  float mx_dm=-INFINITY, mx_curv=-INFINITY, nmn_curv=-INFINITY, nmn_cos=-INFINITY;
  #pragma unroll
  for (int j=0;j<MD;j++){ su[j]=0.f; pd[j]=0.f; cur[j]=0.f; }

  for (int c=0; c<NCHUNK; c++){
    __syncwarp();
    // ---- stage chunk: 32 traj x 80 floats = 640 float4, flattened, MLP=20 ----
    #pragma unroll
    for (int r32=0; r32<20; r32++){
      int q = r32*32 + t;
      int tt = q/20;
      int off4 = q - tt*20;
      float4 v = make_float4(0.f,0.f,0.f,0.f);
      if (tt < tmax)
        v = *(const float4*)(coords + (size_t)(base+tt)*(S*MD) + c*CHF + off4*4);
      float* dst = shC[w] + tt*CST + off4*4;
      *(float2*)(dst)   = make_float2(v.x, v.y);
      *(float2*)(dst+2) = make_float2(v.z, v.w);
    }
    __syncwarp();

    // ---- process CH rows ----
    #pragma unroll
    for (int r=0; r<CH; r++){
      int gi = c*CH + r;
      float nxt[MD];
      #pragma unroll
      for (int j2=0;j2<5;j2++){
        float2 p = *(const float2*)(myrow + r*MD + j2*2);
        nxt[2*j2]=p.x; nxt[2*j2+1]=p.y;
      }
      if (gi < n){
        #pragma unroll
        for (int j=0;j<MD;j++){ sc += nxt[j]; scq = fmaf(nxt[j],nxt[j],scq); }
      }
      if (c==0 && r==0){
        #pragma unroll
        for (int j=0;j<MD;j++) cur[j]=nxt[j];
      } else {
        int k = gi - 1;
        float d[MD]; float dsq=0.f;
        #pragma unroll
        for (int j=0;j<MD;j++){ d[j]=nxt[j]-cur[j]; dsq=fmaf(d[j],d[j],dsq); }
        float rs   = rsqrtf(fmaxf(dsq,1e-30f));
        float dmag = (dsq>0.f) ? dsq*rs : 0.f;
        float inv  = __fdividef(1.f, fmaxf(dmag,1e-8f));
        bool kv = (k < m);
        if (kv){
          s_dm += dmag; s_dmsq += dsq;
          if (k < half+1) s_f += dmag;
          if (k >= half)  s_s += dmag;
          mx_dm = fmaxf(mx_dm, dmag);
          #pragma unroll
          for (int j=0;j<MD;j++) su[j] = fmaf(d[j], inv, su[j]);
          s_usq = fmaf(dsq, inv*inv, s_usq);
        }
        if (gi >= 2){
          float dot=0.f;
          #pragma unroll
          for (int j=0;j<MD;j++) dot = fmaf(pd[j], d[j], dot);
          float cs = dot*pinv*inv, cv = 1.f-cs;
          if (kv){
            s_curv += cv; s_curvsq = fmaf(cv,cv,s_curvsq);
            mx_curv = fmaxf(mx_curv, cv); nmn_curv = fmaxf(nmn_curv, -cv);
            s_cos += cs; nmn_cos = fmaxf(nmn_cos, -cs);
            if (cs < 0.f) s_neg += 1.f;
          }
          // padded curvs: q=k-1 in 0..8  (k in 1..9 -> chunks 0,1 only)
          if (((c==0) || (c==1 && r<3)) && k<=9 && act)
            g_featT[(size_t)(50+k)*B + b] = kv ? cv : 0.f;
        }
        // padded deltas: k<3 (chunk 0, rows 1..3; always valid since m>=3)
        if (c==0 && r>=1 && r<=3 && act){
          #pragma unroll
          for (int j=0;j<MD;j++) g_featT[(size_t)(21+k*MD+j)*B + b] = d[j];
        }
        #pragma unroll
        for (int j=0;j<MD;j++){ pd[j]=d[j]; cur[j]=nxt[j]; }
        pinv = inv;
      }
    }
  }

  // ---- scalar features: fully parallel per lane ----
  if (act){
    const float* cb = coords + (size_t)b*(S*MD);
    float td=0.f;
    #pragma unroll
    for (int j=0;j<MD;j++){
      float diff = __ldg(cb + (n-1)*MD + j) - __ldg(cb + j);
      td = fmaf(diff,diff,td);
    }
    float mf  = (float)m;
    float ncf = (float)(n-2);
    float cnt = (float)(n*MD);
    float rncf = __fdividef(1.f, ncf);

    float mean_coord = __fdividef(sc, cnt);
    float coord_var  = __fdividef(scq - cnt*mean_coord*mean_coord, cnt-1.f);
    float std_coord  = fsqrt_fast(fmaxf(coord_var,1e-30f));

    float mean_dm = __fdividef(s_dm, mf);
    float dm_var  = __fdividef(s_dmsq - mf*mean_dm*mean_dm, fmaxf(mf-1.f,1.f));
    float std_dm  = fsqrt_fast(fmaxf(dm_var,1e-30f));   // m>=3 always

    float mean_curv = s_curv * rncf;
    float curv_var  = __fdividef(s_curvsq - ncf*mean_curv*mean_curv, fmaxf(ncf-1.f,1.f));
    float std_curv  = (ncf>1.f) ? fsqrt_fast(fmaxf(curv_var,1e-30f)) : 0.f;

    float total_disp = (td>0.f) ? fsqrt_fast(fmaxf(td,1e-30f)) : 0.f;

    float ssq=0.f;
    #pragma unroll
    for (int j=0;j<MD;j++) ssq = fmaf(su[j],su[j],ssq);
    float npairs      = mf*(mf-1.f)*0.5f;
    float parallelism = 0.5f*(ssq - s_usq)*__fdividef(1.f, fmaxf(npairs,1.f));

    float rpl = __fdividef(1.f, s_dm+1e-9f);
    float disp_ratio  = total_disp * rpl;
    float loop_score  = 1.f - total_disp * rpl;
    float fh  = __fdividef(s_f, (float)(half+1));
    float sh2 = __fdividef(s_s, (float)(m-half));
    float rfh = __fdividef(1.f, fh+1e-9f);
    float convergence = (fh-sh2)*rfh;
    float cascade     = (sh2-fh)*rfh;
    float mean_cos    = s_cos * rncf;
    float dir_changes = s_neg * __fdividef(1.f, fmaxf(ncf,1.f));
    float jump        = (mean_dm>1e-9f) ? __fdividef(mx_dm, mean_dm) : 1.f;

    size_t Bs = (size_t)B;
    g_featT[ 0*Bs+b]=total_disp;  g_featT[ 1*Bs+b]=s_dm;
    g_featT[ 2*Bs+b]=disp_ratio;  g_featT[ 3*Bs+b]=(float)n*0.1f;
    g_featT[ 4*Bs+b]=mean_curv;   g_featT[ 5*Bs+b]=mx_curv;
    g_featT[ 6*Bs+b]=std_curv;    g_featT[ 7*Bs+b]=mx_curv-(-nmn_curv);
    g_featT[ 8*Bs+b]=mean_cos;    g_featT[ 9*Bs+b]=-nmn_cos;
    g_featT[10*Bs+b]=dir_changes; g_featT[11*Bs+b]=disp_ratio;
    g_featT[12*Bs+b]=loop_score;  g_featT[13*Bs+b]=convergence;
    g_featT[14*Bs+b]=parallelism; g_featT[15*Bs+b]=jump;
    g_featT[16*Bs+b]=cascade;     g_featT[17*Bs+b]=mean_dm;
    g_featT[18*Bs+b]=std_dm;      g_featT[19*Bs+b]=mean_coord;
    g_featT[20*Bs+b]=std_coord;
  }
}

// ============ gemvB: GEMV (60x48) + LayerNorm + exact GELU ============
__global__ __launch_bounds__(GW*32)
void gemvB(const float* __restrict__ bias, const float* __restrict__ ln_w,
           const float* __restrict__ ln_b, float* __restrict__ out, int B)
{
  __shared__ float4 shWt4[H*17];        // 13KB, straight copy of g_WtP
  __shared__ float shB[H], shLw[H], shLb[H];
  __shared__ float fT[GW][NF*GT];       // [k][t] per warp

  int tid = threadIdx.x;
  const float4* wsrc = (const float4*)g_WtP;
  #pragma unroll
  for (int i=tid; i<H*17; i+=GW*32) shWt4[i] = wsrc[i];
  if (tid < H){ shB[tid]=bias[tid]; shLw[tid]=ln_w[tid]; shLb[tid]=ln_b[tid]; }
  __syncthreads();

  int w = tid>>5, l = tid&31;
  int b0 = (blockIdx.x*GW + w)*GT;
  if (b0 >= B) return;

  bool full = ((B & 3)==0) && (b0 + GT <= B);
  if (l < 30){
    if (full){
      float4 va = *(const float4*)&g_featT[(size_t)l*B + b0];
      float4 vb = *(const float4*)&g_featT[(size_t)(l+30)*B + b0];
      ((float4*)fT[w])[l]    = va;
      ((float4*)fT[w])[l+30] = vb;
    } else {
      for (int kk=0; kk<GT; kk++){
        float va = (b0+kk<B) ? g_featT[(size_t)l*B + b0+kk]      : 0.f;
        float vb = (b0+kk<B) ? g_featT[(size_t)(l+30)*B + b0+kk] : 0.f;
        fT[w][l*4+kk]      = va;
        fT[w][(l+30)*4+kk] = vb;
      }
    }
  }
  __syncwarp();

  float h0a[GT], h1a[GT];
  #pragma unroll
  for (int tt=0;tt<GT;tt++){ h0a[tt]=shB[l]; h1a[tt]=(l<16)?shB[l+32]:0.f; }
  const float* fw = fT[w];
  #pragma unroll
  for (int k4=0; k4<15; k4++){
    float4 w0 = shWt4[l*17 + k4];
    float4 w1 = make_float4(0.f,0.f,0.f,0.f);
    if (l<16) w1 = shWt4[(l+32)*17 + k4];
    #pragma unroll
    for (int tt=0;tt<GT;tt++){
      float fx = fw[(4*k4+0)*4+tt], fy = fw[(4*k4+1)*4+tt];
      float fz = fw[(4*k4+2)*4+tt], fv = fw[(4*k4+3)*4+tt];
      h0a[tt] = fmaf(fx,w0.x,fmaf(fy,w0.y,fmaf(fz,w0.z,fmaf(fv,w0.w,h0a[tt]))));
      h1a[tt] = fmaf(fx,w1.x,fmaf(fy,w1.y,fmaf(fz,w1.z,fmaf(fv,w1.w,h1a[tt]))));
    }
  }

  #pragma unroll
  for (int tt=0;tt<GT;tt++){
    int b = b0 + tt;
    if (b >= B) break;
    float ss = h0a[tt] + ((l<16) ? h1a[tt] : 0.f);
    float mu = wsum(ss)*(1.f/48.f);
    float d0 = h0a[tt]-mu, d1 = h1a[tt]-mu;
    float vs = d0*d0 + ((l<16) ? d1*d1 : 0.f);
    float var = wsum(vs)*(1.f/48.f);
    float iv  = rsqrtf(var+1e-5f);
    float g0 = d0*iv*shLw[l]+shLb[l];
    out[(size_t)b*H + l] = 0.5f*g0*(1.f+erff(g0*0.70710678118654752f));
    if (l<16){
      float g1 = d1*iv*shLw[l+32]+shLb[l+32];
      out[(size_t)b*H + l+32] = 0.5f*g1*(1.f+erff(g1*0.70710678118654752f));
    }
  }
}

extern "C" void kernel_launch(void* const* d_in, const int* in_sizes, int n_in,
                              void* d_out, int out_size) {
  const float* coords = (const float*)d_in[0];
  const int*   lengths= (const int*)  d_in[1];
  const float* W      = (const float*)d_in[2];
  const float* bias   = (const float*)d_in[3];
  const float* ln_w   = (const float*)d_in[4];
  const float* ln_b   = (const float*)d_in[5];
  float* out = (float*)d_out;
  int B = in_sizes[0] / (S*MD);

  wprep<<<(H*68 + 255)/256, 256>>>(W);
  int gridA = (B + FW*32 - 1) / (FW*32);
  featA<<<gridA, FW*32>>>(coords, lengths, B);
  int gridB = (B + GW*GT - 1) / (GW*GT);
  gemvB<<<gridB, GW*32>>>(bias, ln_w, ln_b, out, B);
}